// round 7
// baseline (speedup 1.0000x reference)
#include <cuda_runtime.h>
#include <math.h>

#define H_IMG   256
#define NUM_V   512
#define NUM_F   1024
#define TPB     256

#define NTILES  256                  // (256/16)^2 tiles of 16x16 px
#define NCHUNK  8                    // power of two (wrap-safe counters)
#define CHUNK   128                  // faces per chunk

#define LOG_EPS (-13.815511f)        // log(1e-6)
#define HI_T    (0.0371693f)         // dist>HI  => contribution == LOG_EPS exactly
#define LO_T    (-0.0448f)           // dist<LO  => |contribution| < 2.1e-9
#define TILE_R  (0.0830f)            // pixel-center half-diagonal of 16px tile
#define SKIP_C  (LO_T - TILE_R)
#define SAT_C   (HI_T + TILE_R)

// Device scratch. Counters never reset: NCHUNK and NTILES are powers of two,
// so (old & (N-1)) == N-1 is wrap-safe across graph replays.
__device__ float4   g_face[NUM_F * 3];             // per-edge (A,B,C,_) per face
__device__ float    g_S[H_IMG * H_IMG * NCHUNK];   // interleaved [pix][chunk]
__device__ float    g_partial[NTILES];
__device__ unsigned g_tile_cnt[NTILES];
__device__ unsigned g_done;

// ---------------------------------------------------------------------------
// K1: project all 1024 faces ONCE.
// Loads of faces/verts are issued BEFORE the cam-dependent basis math so the
// gather latency overlaps the divide chain. All divides via MUFU (__fdividef);
// degenerate edges keep the +1e-8 form so il=1e8 (NOT inf) -> d=0, matching
// the reference's fminf/fmaxf behavior exactly.
// ---------------------------------------------------------------------------
__global__ void __launch_bounds__(TPB)
setup_kernel(const float* __restrict__ verts,
             const int*   __restrict__ faces,
             const float* __restrict__ cam)
{
    const int f = blockIdx.x * TPB + threadIdx.x;
    if (f >= NUM_F) return;

    // Independent gathers first (overlap with everything below)
    int   vi0 = __ldg(&faces[f*3 + 0]);
    int   vi1 = __ldg(&faces[f*3 + 1]);
    int   vi2 = __ldg(&faces[f*3 + 2]);
    float v0x = __ldg(&verts[vi0*3 + 0]), v0y = __ldg(&verts[vi0*3 + 1]), v0z = __ldg(&verts[vi0*3 + 2]);
    float v1x = __ldg(&verts[vi1*3 + 0]), v1y = __ldg(&verts[vi1*3 + 1]), v1z = __ldg(&verts[vi1*3 + 2]);
    float v2x = __ldg(&verts[vi2*3 + 0]), v2y = __ldg(&verts[vi2*3 + 1]), v2z = __ldg(&verts[vi2*3 + 2]);

    float ex = __ldg(&cam[0]), ey = __ldg(&cam[1]), ez = __ldg(&cam[2]);

    // camera basis
    float rnl = __fdividef(1.0f, sqrtf(ex*ex + ey*ey + ez*ez) + 1e-8f);
    float zx = -ex*rnl, zy = -ey*rnl, zz = -ez*rnl;
    float rcl = __fdividef(1.0f, sqrtf(zz*zz + zx*zx) + 1e-8f);
    float xax = zz*rcl, xay = 0.0f, xaz = -zx*rcl;  // normalize(cross(up,z))
    float yx = zy*xaz - zz*xay;
    float yy = zz*xax - zx*xaz;
    float yz = zx*xay - zy*xax;
    float ryl = __fdividef(1.0f, sqrtf(yx*yx + yy*yy + yz*yz) + 1e-8f);
    yx *= ryl; yy *= ryl; yz *= ryl;

    const float t = 0.57735026918962576f;   // tan(30 deg)

    float vx[3] = {v0x, v1x, v2x};
    float vy[3] = {v0y, v1y, v2y};
    float vz[3] = {v0z, v1z, v2z};

    float sx[3], sy[3];
    bool valid = true;
    #pragma unroll
    for (int k = 0; k < 3; k++) {
        float px = vx[k] - ex;
        float py = vy[k] - ey;
        float pz = vz[k] - ez;
        float X = px*xax + py*xay + pz*xaz;
        float Y = px*yx  + py*yy  + pz*yz;
        float Z = px*zx  + py*zy  + pz*zz;
        valid = valid && (Z > 0.001f);
        float rden = __fdividef(1.0f, Z*t + 1e-8f);
        sx[k] = X * rden;
        sy[k] = Y * rden;
    }

    #pragma unroll
    for (int k = 0; k < 3; k++) {
        int a = k;
        int b = (k == 2) ? 0 : (k + 1);
        float eex = sx[b] - sx[a];
        float eey = sy[b] - sy[a];
        float il  = __fdividef(1.0f, sqrtf(eex*eex + eey*eey) + 1e-8f);
        float A = -eey * il;
        float B =  eex * il;
        float C = (eey * sx[a] - eex * sy[a]) * il;
        if (!valid) {                 // sentinel: dist=-1e30 -> always skipped
            A = 0.0f; B = 0.0f;
            C = (k == 2) ? 1e30f : -1e30f;
        }
        g_face[f*3 + k] = make_float4(A, B, C, 0.0f);
    }
}

__device__ __forceinline__ float face_dist(const float4 e0, const float4 e1,
                                           const float4 e2, float qx, float qy)
{
    float d0 = fmaf(e0.x, qx, fmaf(e0.y, qy, e0.z));
    float d1 = fmaf(e1.x, qx, fmaf(e1.y, qy, e1.z));
    float d2 = fmaf(e2.x, qx, fmaf(e2.y, qy, e2.z));
    float dmin = fminf(fminf(d0, d1), d2);
    float dmax = fmaxf(fmaxf(d0, d1), d2);
    return fmaxf(dmin, -dmax);
}

// ---------------------------------------------------------------------------
// K2: render + fused combine/finish. Grid (NTILES, NCHUNK) = (256, 8).
//   B1: classify this chunk's 128 faces straight from L2-hot g_face
//   B2: compact ONLY band faces into smem (deterministic warp-prefix bases)
//   B3: uniform per-pixel loop over the compacted list -> g_S interleaved
//   B4: 8th block per tile (election) combines chunks, SSE -> g_partial
//   B5: 256th tile-finisher: fixed-order 256-way tree + distance penalty
// All FP sum orders fixed => deterministic. No spin-waits => no deadlock.
// ---------------------------------------------------------------------------
__global__ void __launch_bounds__(TPB)
render_kernel(const float* __restrict__ img,
              const float* __restrict__ cam,
              float*       __restrict__ out)
{
    __shared__ float4   sband[CHUNK * 3];   // compacted band faces (<=6KB)
    __shared__ int      wcnt[4];
    __shared__ int      wsat[4];
    __shared__ float    red[8];
    __shared__ unsigned elect;

    const int tid  = threadIdx.x;
    const int tile = blockIdx.x;
    const int c    = blockIdx.y;
    const int w    = tid >> 5, lane = tid & 31;

    const int tx = tile & 15, ty = tile >> 4;
    const float cx =  ((tx * 16 + 8.0f) / 128.0f) - 1.0f;
    const float cy = -(((ty * 16 + 8.0f) / 128.0f) - 1.0f);

    // ---- B1/B2: classify 1 face/thread (threads 0..127), compact band ----
    float4 e0, e1, e2;
    unsigned isband = 0u;
    int pos = 0;
    if (tid < CHUNK) {
        const int gf = (c * CHUNK + tid) * 3;
        e0 = g_face[gf + 0];
        e1 = g_face[gf + 1];
        e2 = g_face[gf + 2];
        float dc = face_dist(e0, e1, e2, cx, cy);
        bool sat  = (dc > SAT_C);
        bool band = (dc > SKIP_C) && !sat;
        unsigned mb = __ballot_sync(0xffffffffu, band);
        unsigned ms = __ballot_sync(0xffffffffu, sat);
        pos = __popc(mb & ((1u << lane) - 1u));
        if (lane == 0) {
            wcnt[w] = __popc(mb);
            wsat[w] = __popc(ms);
        }
        isband = band ? 1u : 0u;
    }
    __syncthreads();

    int base1 = wcnt[0];
    int base2 = base1 + wcnt[1];
    int base3 = base2 + wcnt[2];
    const int n_total   = base3 + wcnt[3];
    const int sat_total = wsat[0] + wsat[1] + wsat[2] + wsat[3];

    if (isband) {
        int base = (w == 0) ? 0 : (w == 1) ? base1 : (w == 2) ? base2 : base3;
        int s = base + pos;
        sband[3*s + 0] = e0;
        sband[3*s + 1] = e1;
        sband[3*s + 2] = e2;
    }
    __syncthreads();

    // ---- B3: per-pixel loop over compacted band list ----
    const int col = tx * 16 + (tid & 15);
    const int row = ty * 16 + (tid >> 4);
    const int pix = row * H_IMG + col;
    const float qx =  ((col + 0.5f) / 128.0f) - 1.0f;
    const float qy = -(((row + 0.5f) / 128.0f) - 1.0f);

    float S   = 0.0f;
    int   cnt = sat_total;

    for (int j = 0; j < n_total; j++) {
        float dist = face_dist(sband[3*j], sband[3*j+1], sband[3*j+2], qx, qy);
        if (dist > HI_T) {
            cnt++;
        } else if (dist > LO_T) {
            // -softplus(x) via MUFU; |err| ~1e-6 << tolerance
            float x = dist * fabsf(dist) * 1e4f;
            float cc = -__logf(fmaf(__expf(x), 1.0f, 1.0f));
            S += fmaxf(cc, LOG_EPS);
        }
    }

    S += (float)cnt * LOG_EPS;
    g_S[pix * NCHUNK + c] = S;     // interleaved: combine reads 2x float4

    // ---- B4 election: 8th arrival for this tile combines it ----
    __threadfence();
    __syncthreads();
    if (tid == 0) elect = atomicAdd(&g_tile_cnt[tile], 1u);
    __syncthreads();
    if ((elect & (NCHUNK - 1)) != (NCHUNK - 1)) return;

    __threadfence();   // acquire side
    const float4* p = (const float4*)&g_S[pix * NCHUNK];
    float4 a = __ldg(&p[0]);   // values are GPU-coherent: written pre-fence,
    float4 b = __ldg(&p[1]);   // observed post-election
    float Ssum = ((a.x + a.y) + (a.z + a.w)) + ((b.x + b.y) + (b.z + b.w));

    float alpha = 1.0f - expf(Ssum);
    float r = __ldg(&img[pix]) - alpha;
    float v = r * r;

    #pragma unroll
    for (int o = 16; o > 0; o >>= 1)
        v += __shfl_down_sync(0xffffffffu, v, o);
    if (lane == 0) red[w] = v;
    __syncthreads();

    if (tid == 0) {
        float bs = 0.0f;
        #pragma unroll
        for (int i = 0; i < 8; i++) bs += red[i];      // fixed order
        g_partial[tile] = bs;
        __threadfence();
        elect = atomicAdd(&g_done, 1u);
    }
    __syncthreads();

    // ---- B5: 256th tile-finisher does the final reduce ----
    if ((elect & (NTILES - 1)) != (NTILES - 1)) return;

    __threadfence();
    __shared__ float fred[TPB];
    fred[tid] = __ldcg(&g_partial[tid]);                  // NTILES == TPB
    __syncthreads();
    #pragma unroll
    for (int o = TPB / 2; o > 0; o >>= 1) {               // fixed-order tree
        if (tid < o) fred[tid] += fred[tid + o];
        __syncthreads();
    }
    if (tid == 0) {
        float ex = __ldg(&cam[0]), ey = __ldg(&cam[1]), ez = __ldg(&cam[2]);
        float d = sqrtf(ex*ex + ey*ey + ez*ez);
        float pen = fmaxf(0.0f, 6.0f - d);
        out[0] = fred[0] * (1.0f + pen);
    }
}

// ---------------------------------------------------------------------------
extern "C" void kernel_launch(void* const* d_in, const int* in_sizes, int n_in,
                              void* d_out, int out_size)
{
    const float* verts = nullptr;
    const int*   faces = nullptr;
    const float* img   = nullptr;
    const float* cam   = nullptr;

    for (int i = 0; i < n_in; i++) {
        switch (in_sizes[i]) {
            case NUM_V * 3:      verts = (const float*)d_in[i]; break;
            case NUM_F * 3:      faces = (const int*)  d_in[i]; break;
            case H_IMG * H_IMG:  img   = (const float*)d_in[i]; break;
            case 3:              cam   = (const float*)d_in[i]; break;
            default: break;
        }
    }

    setup_kernel<<<NUM_F / TPB, TPB>>>(verts, faces, cam);

    dim3 grid(NTILES, NCHUNK);
    render_kernel<<<grid, TPB>>>(img, cam, (float*)d_out);
}